// round 6
// baseline (speedup 1.0000x reference)
#include <cuda_runtime.h>
#include <cstdint>

// ---------------------------------------------------------------------------
// QuantumNeuralNetwork: fused MLP + 4-qubit expval + classifier
//
// Math reduction: variational circuit has batch-shared weights, so
//   <Z0> = e^T Re(U' Z0 U) e  with U the fixed 16x16 circuit unitary and
//   e the real RY-embedding product state. M = Re(U' Z0 U) is precomputed
//   once per launch by build_M_kernel.
// ---------------------------------------------------------------------------

#define XS 132   // padded smem row stride for transposed input tiles
#define SMEM_FLOATS (48*XS + 16*XS + 3072 + 512 + 256 + 128 + 64 + 32 + 4 + 256 + 68)

__device__ __align__(16) float g_M[256];

// ---------------------------------------------------------------------------
// Prologue: build M[16][16] = Re(U^dagger Z0 U) from qweights [2][4][3].
// 16 threads; thread k simulates the variational circuit on basis state |k>.
// Index convention: n = q0*8 + q1*4 + q2*2 + q3 (qubit i <-> bit (3-i)).
// ---------------------------------------------------------------------------
__global__ void build_M_kernel(const float* __restrict__ qw) {
    __shared__ float Ure[16][16], Uim[16][16];
    const int k = threadIdx.x;  // column index 0..15
    float vr[16], vi[16];
#pragma unroll
    for (int n = 0; n < 16; n++) { vr[n] = (n == k) ? 1.f : 0.f; vi[n] = 0.f; }

    for (int l = 0; l < 2; l++) {
        for (int i = 0; i < 4; i++) {
            float phi = qw[(l*4 + i)*3 + 0];
            float th  = qw[(l*4 + i)*3 + 1];
            float om  = qw[(l*4 + i)*3 + 2];
            float ct = cosf(0.5f*th), st = sinf(0.5f*th);
            float sp, cp, sm, cm;
            sincosf(0.5f*(phi + om), &sp, &cp);
            sincosf(0.5f*(phi - om), &sm, &cm);
            // U00=e^{-i(phi+om)/2} ct ; U01=-e^{+i(phi-om)/2} st
            // U10=e^{-i(phi-om)/2} st ; U11=e^{+i(phi+om)/2} ct
            float u00r =  cp*ct, u00i = -sp*ct;
            float u01r = -cm*st, u01i = -sm*st;
            float u10r =  cm*st, u10i = -sm*st;
            float u11r =  cp*ct, u11i =  sp*ct;
            int mask = 1 << (3 - i);
#pragma unroll
            for (int n = 0; n < 16; n++) {
                if (n & mask) continue;
                int n1 = n | mask;
                float r0 = vr[n],  i0 = vi[n];
                float r1 = vr[n1], i1 = vi[n1];
                vr[n]  = u00r*r0 - u00i*i0 + u01r*r1 - u01i*i1;
                vi[n]  = u00r*i0 + u00i*r0 + u01r*i1 + u01i*r1;
                vr[n1] = u10r*r0 - u10i*i0 + u11r*r1 - u11i*i1;
                vi[n1] = u10r*i0 + u10i*r0 + u11r*i1 + u11i*r1;
            }
        }
        // CZ chain on (qubit i, qubit i+1), i = 0..2
        for (int i = 0; i < 3; i++) {
            int m1 = 1 << (3 - i), m2 = 1 << (2 - i);
#pragma unroll
            for (int n = 0; n < 16; n++)
                if ((n & m1) && (n & m2)) { vr[n] = -vr[n]; vi[n] = -vi[n]; }
        }
    }
#pragma unroll
    for (int n = 0; n < 16; n++) { Ure[n][k] = vr[n]; Uim[n][k] = vi[n]; }
    __syncthreads();
    // M[j][k] = sum_b z(b) Re( conj(U[b][j]) * U[b][k] ), z(b) = (b&8) ? -1 : +1
#pragma unroll
    for (int j = 0; j < 16; j++) {
        float acc = 0.f;
#pragma unroll
        for (int b = 0; b < 16; b++) {
            float z = (b & 8) ? -1.f : 1.f;
            acc += z * (Ure[b][j]*Ure[b][k] + Uim[b][j]*Uim[b][k]);
        }
        g_M[j*16 + k] = acc;
    }
}

// ---------------------------------------------------------------------------
// Main fused kernel: 128 threads handle 128 samples per block.
// Phase 1: image MLP1 as a 128x64xK48 SGEMM microtile (TM=8, TN=8).
// Phase 2: text  MLP1 as a 128x32xK16 SGEMM microtile (TM=8, TN=4).
// Second layers folded into per-thread partials, shfl-reduced across the
// 8 k-chunk threads. Quantum + classifier: 1 sample/thread via smem feats.
// ---------------------------------------------------------------------------
__global__ __launch_bounds__(128) void qnn_kernel(
    const float* __restrict__ text, const float* __restrict__ image,
    const float* __restrict__ tW1,  const float* __restrict__ tb1,
    const float* __restrict__ tW2,  const float* __restrict__ tb2,
    const float* __restrict__ iW1,  const float* __restrict__ ib1,
    const float* __restrict__ iW2,  const float* __restrict__ ib2,
    const float* __restrict__ cW1,  const float* __restrict__ cb1,
    const float* __restrict__ cW2,  const float* __restrict__ cb2,
    float* __restrict__ out)
{
    extern __shared__ float smf[];
    float* xTi  = smf;                 // [48][XS] transposed image tile
    float* xTt  = xTi  + 48*XS;        // [16][XS] transposed text tile
    float* wI1s = xTt  + 16*XS;        // [48][64]
    float* wT1s = wI1s + 3072;         // [16][32]
    float* wI2t = wT1s + 512;          // [4][64]  (transposed iW2)
    float* wT2t = wI2t + 256;          // [4][32]  (transposed tW2)
    float* ib1s = wT2t + 128;          // [64]
    float* tb1s = ib1s + 64;           // [32]
    float* b2s  = tb1s + 32;           // [4] = ib2 + tb2
    float* Ms   = b2s  + 4;            // [16][16]
    float* cls  = Ms   + 256;          // cW1[16] cb1[16] cW2[32] cb2[2]
    float* feats = xTi;                // aliased after GEMMs: [128][4]

    const int tid = threadIdx.x;
    const size_t base = (size_t)blockIdx.x * 128;

    // ---- stage inputs + weights into shared ----
    {
        const float4* ig = (const float4*)(image + base * 48);
#pragma unroll
        for (int it = 0; it < 12; it++) {
            int idx = it*128 + tid;
            float4 v = ig[idx];
            int s = idx / 12;
            int kq = idx - s*12;
            float* p = &xTi[(4*kq)*XS + s];
            p[0] = v.x; p[XS] = v.y; p[2*XS] = v.z; p[3*XS] = v.w;
        }
        const float4* tg = (const float4*)(text + base * 16);
#pragma unroll
        for (int it = 0; it < 4; it++) {
            int idx = it*128 + tid;
            float4 v = tg[idx];
            int s = idx >> 2;
            int kq = idx & 3;
            float* p = &xTt[(4*kq)*XS + s];
            p[0] = v.x; p[XS] = v.y; p[2*XS] = v.z; p[3*XS] = v.w;
        }
#pragma unroll
        for (int it = 0; it < 6; it++)
            ((float4*)wI1s)[it*128 + tid] = ((const float4*)iW1)[it*128 + tid];
        ((float4*)wT1s)[tid] = ((const float4*)tW1)[tid];
        if (tid < 64) {
            float4 w = ((const float4*)iW2)[tid];   // row tid of iW2[64][4]
            wI2t[tid] = w.x; wI2t[64+tid] = w.y; wI2t[128+tid] = w.z; wI2t[192+tid] = w.w;
            ib1s[tid] = ib1[tid];
            ((float4*)Ms)[tid] = ((const float4*)g_M)[tid];
        }
        if (tid < 32) {
            float4 w = ((const float4*)tW2)[tid];   // row tid of tW2[32][4]
            wT2t[tid] = w.x; wT2t[32+tid] = w.y; wT2t[64+tid] = w.z; wT2t[96+tid] = w.w;
            tb1s[tid] = tb1[tid];
        }
        if (tid < 16) {
            cls[tid] = cW1[tid]; cls[16+tid] = cb1[tid];
            cls[32+2*tid] = cW2[2*tid]; cls[33+2*tid] = cW2[2*tid+1];
        }
        if (tid < 4) b2s[tid] = ib2[tid] + tb2[tid];
        if (tid < 2) cls[64+tid] = cb2[tid];
    }
    __syncthreads();

    const int trow = tid >> 3;        // 0..15 : sample group
    const int tcol = tid & 7;         // 0..7  : neuron / k-chunk group
    const int m0 = trow * 8;

    // ---- image MLP1: 128x64, K=48, microtile 8x8 ----
    const int n0 = tcol * 8;
    float acc[8][8];
#pragma unroll
    for (int i = 0; i < 8; i++)
#pragma unroll
        for (int j = 0; j < 8; j++) acc[i][j] = 0.f;

#pragma unroll 8
    for (int k = 0; k < 48; k++) {
        float4 a0 = *(const float4*)&xTi[k*XS + m0];
        float4 a1 = *(const float4*)&xTi[k*XS + m0 + 4];
        float4 b0 = *(const float4*)&wI1s[k*64 + n0];
        float4 b1 = *(const float4*)&wI1s[k*64 + n0 + 4];
        float a[8] = {a0.x,a0.y,a0.z,a0.w,a1.x,a1.y,a1.z,a1.w};
        float b[8] = {b0.x,b0.y,b0.z,b0.w,b1.x,b1.y,b1.z,b1.w};
#pragma unroll
        for (int i = 0; i < 8; i++)
#pragma unroll
            for (int j = 0; j < 8; j++)
                acc[i][j] = fmaf(a[i], b[j], acc[i][j]);
    }

    // ---- fold into imf partials: relu(h2)·iW2 over this thread's 8 neurons ----
    float pv[8][4];
#pragma unroll
    for (int i = 0; i < 8; i++)
#pragma unroll
        for (int n = 0; n < 4; n++) pv[i][n] = 0.f;

#pragma unroll
    for (int j = 0; j < 8; j++) {
        int nj = n0 + j;
        float w0 = wI2t[nj], w1 = wI2t[64+nj], w2 = wI2t[128+nj], w3 = wI2t[192+nj];
        float bj = ib1s[nj];
#pragma unroll
        for (int i = 0; i < 8; i++) {
            float h = fmaxf(acc[i][j] + bj, 0.f);
            pv[i][0] = fmaf(h, w0, pv[i][0]);
            pv[i][1] = fmaf(h, w1, pv[i][1]);
            pv[i][2] = fmaf(h, w2, pv[i][2]);
            pv[i][3] = fmaf(h, w3, pv[i][3]);
        }
    }

    // ---- text MLP1: 128x32, K=16, microtile 8x4 ----
    const int t0 = tcol * 4;
    float acc2[8][4];
#pragma unroll
    for (int i = 0; i < 8; i++)
#pragma unroll
        for (int j = 0; j < 4; j++) acc2[i][j] = 0.f;

#pragma unroll
    for (int k = 0; k < 16; k++) {
        float4 a0 = *(const float4*)&xTt[k*XS + m0];
        float4 a1 = *(const float4*)&xTt[k*XS + m0 + 4];
        float4 b  = *(const float4*)&wT1s[k*32 + t0];
        float a[8] = {a0.x,a0.y,a0.z,a0.w,a1.x,a1.y,a1.z,a1.w};
#pragma unroll
        for (int i = 0; i < 8; i++) {
            acc2[i][0] = fmaf(a[i], b.x, acc2[i][0]);
            acc2[i][1] = fmaf(a[i], b.y, acc2[i][1]);
            acc2[i][2] = fmaf(a[i], b.z, acc2[i][2]);
            acc2[i][3] = fmaf(a[i], b.w, acc2[i][3]);
        }
    }
#pragma unroll
    for (int j = 0; j < 4; j++) {
        int nj = t0 + j;
        float w0 = wT2t[nj], w1 = wT2t[32+nj], w2 = wT2t[64+nj], w3 = wT2t[96+nj];
        float bj = tb1s[nj];
#pragma unroll
        for (int i = 0; i < 8; i++) {
            float h = fmaxf(acc2[i][j] + bj, 0.f);
            pv[i][0] = fmaf(h, w0, pv[i][0]);
            pv[i][1] = fmaf(h, w1, pv[i][1]);
            pv[i][2] = fmaf(h, w2, pv[i][2]);
            pv[i][3] = fmaf(h, w3, pv[i][3]);
        }
    }

    // ---- reduce partials across the 8 k-chunk lanes (consecutive lanes) ----
#pragma unroll
    for (int i = 0; i < 8; i++)
#pragma unroll
        for (int n = 0; n < 4; n++) {
            float v = pv[i][n];
            v += __shfl_xor_sync(0xffffffffu, v, 4);
            v += __shfl_xor_sync(0xffffffffu, v, 2);
            v += __shfl_xor_sync(0xffffffffu, v, 1);
            pv[i][n] = v;
        }

    __syncthreads();   // everyone done reading xTi/xTt before feats alias write
    if (tcol == 0) {
        float4 bb = *(const float4*)b2s;
#pragma unroll
        for (int i = 0; i < 8; i++) {
            float4 fo;
            fo.x = 0.5f * (pv[i][0] + bb.x);
            fo.y = 0.5f * (pv[i][1] + bb.y);
            fo.z = 0.5f * (pv[i][2] + bb.z);
            fo.w = 0.5f * (pv[i][3] + bb.w);
            *(float4*)&feats[(m0 + i) * 4] = fo;
        }
    }
    __syncthreads();

    // ---- quantum expval + classifier: one sample per thread ----
    float4 f = *(const float4*)&feats[tid * 4];
    float c0, q0s, c1, q1s, c2, q2s, c3, q3s;
    __sincosf(0.5f*f.x, &q0s, &c0);
    __sincosf(0.5f*f.y, &q1s, &c1);
    __sincosf(0.5f*f.z, &q2s, &c2);
    __sincosf(0.5f*f.w, &q3s, &c3);

    float p01[4] = {c0*c1, c0*q1s, q0s*c1, q0s*q1s};
    float p23[4] = {c2*c3, c2*q3s, q2s*c3, q2s*q3s};
    float e[16];
#pragma unroll
    for (int a = 0; a < 4; a++)
#pragma unroll
        for (int b = 0; b < 4; b++) e[a*4+b] = p01[a] * p23[b];

    float q = 0.f;
#pragma unroll
    for (int j = 0; j < 16; j++) {
        const float4* Mr = (const float4*)&Ms[j*16];
        float4 r0 = Mr[0], r1 = Mr[1], r2 = Mr[2], r3 = Mr[3];
        float tj = r0.x*e[0] + r0.y*e[1] + r0.z*e[2] + r0.w*e[3]
                 + r1.x*e[4] + r1.y*e[5] + r1.z*e[6] + r1.w*e[7]
                 + r2.x*e[8] + r2.y*e[9] + r2.z*e[10] + r2.w*e[11]
                 + r3.x*e[12] + r3.y*e[13] + r3.z*e[14] + r3.w*e[15];
        q = fmaf(e[j], tj, q);
    }

    float o0 = cls[64], o1 = cls[65];
#pragma unroll
    for (int m = 0; m < 16; m++) {
        float h = fmaxf(fmaf(q, cls[m], cls[16+m]), 0.f);
        o0 = fmaf(h, cls[32+2*m], o0);
        o1 = fmaf(h, cls[33+2*m], o1);
    }
    float2 res; res.x = o0; res.y = o1;
    ((float2*)out)[base + tid] = res;
}

// ---------------------------------------------------------------------------
extern "C" void kernel_launch(void* const* d_in, const int* in_sizes, int n_in,
                              void* d_out, int out_size) {
    const float* text = (const float*)d_in[0];
    const float* image= (const float*)d_in[1];
    const float* tW1  = (const float*)d_in[2];
    const float* tb1  = (const float*)d_in[3];
    const float* tW2  = (const float*)d_in[4];
    const float* tb2  = (const float*)d_in[5];
    const float* iW1  = (const float*)d_in[6];
    const float* ib1  = (const float*)d_in[7];
    const float* iW2  = (const float*)d_in[8];
    const float* ib2  = (const float*)d_in[9];
    const float* qw   = (const float*)d_in[10];
    const float* cW1  = (const float*)d_in[11];
    const float* cb1  = (const float*)d_in[12];
    const float* cW2  = (const float*)d_in[13];
    const float* cb2  = (const float*)d_in[14];
    float* out = (float*)d_out;

    const int B = in_sizes[0] / 16;
    const int grid = B / 128;
    const size_t smem = SMEM_FLOATS * sizeof(float);

    cudaFuncSetAttribute(qnn_kernel, cudaFuncAttributeMaxDynamicSharedMemorySize, (int)smem);

    build_M_kernel<<<1, 16>>>(qw);
    qnn_kernel<<<grid, 128, smem>>>(text, image, tW1, tb1, tW2, tb2,
                                    iW1, ib1, iW2, ib2,
                                    cW1, cb1, cW2, cb2, out);
}